// round 3
// baseline (speedup 1.0000x reference)
#include <cuda_runtime.h>
#include <cuda_bf16.h>
#include <math.h>

#define NMAX 50000
#define EMAX 600000
#define GMAX 128
#define WS_LD 132

// ---------------- scratch (static device globals: allowed) ----------------
__device__ __align__(16) float g_xn[NMAX * 128];
__device__ __align__(16) float g_mean[NMAX * 128];
__device__ __align__(16) float g_t[NMAX * 128];
__device__ __align__(16) float g_h1[NMAX * 128];
__device__ __align__(16) float g_h[NMAX * 128];
__device__ __align__(16) float g_pooled[GMAX * 128];
__device__ int g_rowptr[NMAX + 1];
__device__ int g_fill[NMAX];
__device__ int g_col[EMAX];
__device__ int g_src[EMAX];
__device__ int g_dst[EMAX];
__device__ int g_batch[NMAX];
__device__ int g_is64;

// ---------------- packed f32x2 helpers (sm_103a) ----------------
__device__ __forceinline__ unsigned long long pk2(float lo, float hi) {
    unsigned long long r;
    asm("mov.b64 %0, {%1,%2};" : "=l"(r) : "f"(lo), "f"(hi));
    return r;
}
__device__ __forceinline__ void fma2(unsigned long long& d, unsigned long long a, unsigned long long b) {
    asm("fma.rn.f32x2 %0, %1, %2, %0;" : "+l"(d) : "l"(a), "l"(b));
}
__device__ __forceinline__ void upk2(unsigned long long v, float& lo, float& hi) {
    asm("mov.b64 {%0,%1}, %2;" : "=f"(lo), "=f"(hi) : "l"(v));
}

// ---------------- dtype probe: are index buffers int64 or int32? ----------------
// Reads first min(1024, count/2) entries as int64 (safe under either layout).
// All-in-range [0, nlimit) => int64. Any out-of-range => int32 (fused pairs).
__global__ void k_detect64(const void* raw, int count, int nlimit, int* flag) {
    __shared__ int ok;
    if (threadIdx.x == 0) ok = 1;
    __syncthreads();
    int m = count / 2 < 1024 ? count / 2 : 1024;
    const long long* p = (const long long*)raw;
    for (int i = threadIdx.x; i < m; i += blockDim.x) {
        long long v = p[i];
        if (v < 0 || v >= (long long)nlimit) ok = 0;
    }
    __syncthreads();
    if (threadIdx.x == 0) *flag = ok;
}

__global__ void k_convert_edges(const void* raw, int E, const int* flag,
                                int* __restrict__ src, int* __restrict__ dst) {
    int e = blockIdx.x * blockDim.x + threadIdx.x;
    if (e >= E) return;
    if (*flag) {
        const long long* p = (const long long*)raw;
        src[e] = (int)p[e];
        dst[e] = (int)p[E + e];
    } else {
        const int* p = (const int*)raw;
        src[e] = p[e];
        dst[e] = p[E + e];
    }
}

__global__ void k_convert_batch(const void* raw, int n, const int* flag, int* __restrict__ b) {
    int i = blockIdx.x * blockDim.x + threadIdx.x;
    if (i >= n) return;
    if (*flag) b[i] = (int)((const long long*)raw)[i];
    else       b[i] = ((const int*)raw)[i];
}

// ---------------- small utility kernels ----------------
__global__ void k_zero_int(int* __restrict__ p, int n) {
    int i = blockIdx.x * blockDim.x + threadIdx.x;
    if (i < n) p[i] = 0;
}
__global__ void k_copy_int(const int* __restrict__ src, int* __restrict__ dst, int n) {
    int i = blockIdx.x * blockDim.x + threadIdx.x;
    if (i < n) dst[i] = src[i];
}

// ---------------- preprocess: row-normalize by row sum ----------------
__global__ void k_preprocess(const float* __restrict__ x, float* __restrict__ xn, int n) {
    int w = (blockIdx.x * blockDim.x + threadIdx.x) >> 5;
    if (w >= n) return;
    int lane = threadIdx.x & 31;
    float4 v = *(const float4*)(x + (size_t)w * 128 + lane * 4);
    float s = v.x + v.y + v.z + v.w;
#pragma unroll
    for (int o = 16; o > 0; o >>= 1) s += __shfl_xor_sync(0xffffffffu, s, o);
    float rinv = (s != 0.f) ? (1.f / s) : 0.f;
    float4 r = make_float4(v.x * rinv, v.y * rinv, v.z * rinv, v.w * rinv);
    *(float4*)(xn + (size_t)w * 128 + lane * 4) = r;
}

// ---------------- CSR build ----------------
__global__ void k_count_deg(const int* __restrict__ dst, int* __restrict__ deg, int E) {
    int e = blockIdx.x * blockDim.x + threadIdx.x;
    if (e < E) atomicAdd(&deg[dst[e]], 1);
}

__global__ void k_scan_deg(const int* __restrict__ deg, int* __restrict__ rowptr, int n) {
    __shared__ int wsum[32];
    __shared__ int s_total;
    int t = threadIdx.x, lane = t & 31, wid = t >> 5;
    int carry = 0;
    for (int base = 0; base < n; base += 1024) {
        int v = (base + t < n) ? deg[base + t] : 0;
        int xv = v;
#pragma unroll
        for (int o = 1; o < 32; o <<= 1) {
            int y = __shfl_up_sync(0xffffffffu, xv, o);
            if (lane >= o) xv += y;
        }
        if (lane == 31) wsum[wid] = xv;
        __syncthreads();
        if (wid == 0) {
            int wv = wsum[lane];
#pragma unroll
            for (int o = 1; o < 32; o <<= 1) {
                int y = __shfl_up_sync(0xffffffffu, wv, o);
                if (lane >= o) wv += y;
            }
            wsum[lane] = wv;
            if (lane == 31) s_total = wv;
        }
        __syncthreads();
        int incl = xv + (wid > 0 ? wsum[wid - 1] : 0);
        if (base + t < n) rowptr[base + t] = carry + incl - v;
        carry += s_total;
        __syncthreads();
    }
    if (t == 0) rowptr[n] = carry;
}

__global__ void k_fill_edges(const int* __restrict__ src, const int* __restrict__ dst,
                             int* __restrict__ fillc, int* __restrict__ col, int E) {
    int e = blockIdx.x * blockDim.x + threadIdx.x;
    if (e < E) {
        int p = atomicAdd(&fillc[dst[e]], 1);
        col[p] = src[e];
    }
}

// ---------------- mean aggregation: warp per dst node, gather-only ----------------
__global__ void k_aggregate(const float* __restrict__ xin, const int* __restrict__ rowptr,
                            const int* __restrict__ col, float* __restrict__ outm, int n) {
    int w = (blockIdx.x * blockDim.x + threadIdx.x) >> 5;
    if (w >= n) return;
    int lane = threadIdx.x & 31;
    int s0 = rowptr[w], s1 = rowptr[w + 1];
    float ax = 0.f, ay = 0.f, az = 0.f, aw = 0.f;
    for (int j = s0; j < s1; ++j) {
        int s = __ldg(&col[j]);
        float4 v = *(const float4*)(xin + (size_t)s * 128 + lane * 4);
        ax += v.x; ay += v.y; az += v.z; aw += v.w;
    }
    float inv = 1.f / fmaxf((float)(s1 - s0), 1.f);
    float4 r = make_float4(ax * inv, ay * inv, az * inv, aw * inv);
    *(float4*)(outm + (size_t)w * 128 + lane * 4) = r;
}

// ---------------- l2norm + leaky, warp per row ----------------
__global__ void k_normleaky(const float* __restrict__ in, float* __restrict__ outp, int n) {
    int w = (blockIdx.x * blockDim.x + threadIdx.x) >> 5;
    if (w >= n) return;
    int lane = threadIdx.x & 31;
    float4 v = *(const float4*)(in + (size_t)w * 128 + lane * 4);
    float ss = v.x * v.x + v.y * v.y + v.z * v.z + v.w * v.w;
#pragma unroll
    for (int o = 16; o > 0; o >>= 1) ss += __shfl_xor_sync(0xffffffffu, ss, o);
    float inv = 1.f / fmaxf(sqrtf(ss), 1e-12f);
    float4 r;
    r.x = v.x * inv; r.x = (r.x >= 0.f) ? r.x : 0.01f * r.x;
    r.y = v.y * inv; r.y = (r.y >= 0.f) ? r.y : 0.01f * r.y;
    r.z = v.z * inv; r.z = (r.z >= 0.f) ? r.z : 0.01f * r.z;
    r.w = v.w * inv; r.w = (r.w >= 0.f) ? r.w : 0.01f * r.w;
    *(float4*)(outp + (size_t)w * 128 + lane * 4) = r;
}

// ---------------- dual GEMM: out = A @ Wa^T + B @ Wb^T (+bias, +leaky) ----------------
__global__ void __launch_bounds__(256, 1)
k_gemm_dual(const float* __restrict__ A, const float* __restrict__ B,
            const float* __restrict__ Wa, const float* __restrict__ Wb, int ldw,
            const float* __restrict__ bias, float* __restrict__ out,
            int n, int do_leaky) {
    extern __shared__ float sm[];
    float* Ws = sm;                  // [256][WS_LD] k-major weights
    float* As = sm + 256 * WS_LD;    // [16][128]   k-major A stage
    int t = threadIdx.x;

    for (int idx = t; idx < 128 * 128; idx += 256) {
        int h = idx >> 7;
        int k = idx & 127;
        Ws[k * WS_LD + h]          = Wa[h * ldw + k];
        Ws[(128 + k) * WS_LD + h]  = Wb[h * ldw + k];
    }

    int tx = t & 15, ty = t >> 4;
    int row0 = blockIdx.x * 128;
    unsigned long long acc[8][4];
#pragma unroll
    for (int i = 0; i < 8; ++i)
#pragma unroll
        for (int j = 0; j < 4; ++j) acc[i][j] = 0ULL;

    for (int kc = 0; kc < 16; ++kc) {
        const float* src = (kc < 8) ? A : B;
        int kbase = (kc & 7) * 16;
        __syncthreads();
#pragma unroll
        for (int j = 0; j < 2; ++j) {
            int idx2 = t * 2 + j;
            int r = idx2 >> 2, seg = idx2 & 3;
            int grow = row0 + r;
            float4 v = make_float4(0.f, 0.f, 0.f, 0.f);
            if (grow < n) v = *(const float4*)(src + (size_t)grow * 128 + kbase + seg * 4);
            As[(seg * 4 + 0) * 128 + r] = v.x;
            As[(seg * 4 + 1) * 128 + r] = v.y;
            As[(seg * 4 + 2) * 128 + r] = v.z;
            As[(seg * 4 + 3) * 128 + r] = v.w;
        }
        __syncthreads();
#pragma unroll
        for (int kk = 0; kk < 16; ++kk) {
            int kg = kc * 16 + kk;
            float4 a0 = *(const float4*)&As[kk * 128 + ty * 8];
            float4 a1 = *(const float4*)&As[kk * 128 + ty * 8 + 4];
            float4 w0 = *(const float4*)&Ws[kg * WS_LD + tx * 8];
            float4 w1 = *(const float4*)&Ws[kg * WS_LD + tx * 8 + 4];
            unsigned long long wp0 = pk2(w0.x, w0.y);
            unsigned long long wp1 = pk2(w0.z, w0.w);
            unsigned long long wp2 = pk2(w1.x, w1.y);
            unsigned long long wp3 = pk2(w1.z, w1.w);
            float av[8] = {a0.x, a0.y, a0.z, a0.w, a1.x, a1.y, a1.z, a1.w};
#pragma unroll
            for (int i = 0; i < 8; ++i) {
                unsigned long long ad = pk2(av[i], av[i]);
                fma2(acc[i][0], ad, wp0);
                fma2(acc[i][1], ad, wp1);
                fma2(acc[i][2], ad, wp2);
                fma2(acc[i][3], ad, wp3);
            }
        }
    }

    float bv[8];
    if (bias) {
        float4 b0 = *(const float4*)(bias + tx * 8);
        float4 b1 = *(const float4*)(bias + tx * 8 + 4);
        bv[0] = b0.x; bv[1] = b0.y; bv[2] = b0.z; bv[3] = b0.w;
        bv[4] = b1.x; bv[5] = b1.y; bv[6] = b1.z; bv[7] = b1.w;
    } else {
#pragma unroll
        for (int j = 0; j < 8; ++j) bv[j] = 0.f;
    }

#pragma unroll
    for (int i = 0; i < 8; ++i) {
        int grow = row0 + ty * 8 + i;
        if (grow >= n) continue;
        float v[8];
        upk2(acc[i][0], v[0], v[1]);
        upk2(acc[i][1], v[2], v[3]);
        upk2(acc[i][2], v[4], v[5]);
        upk2(acc[i][3], v[6], v[7]);
#pragma unroll
        for (int j = 0; j < 8; ++j) {
            v[j] += bv[j];
            if (do_leaky) v[j] = (v[j] >= 0.f) ? v[j] : 0.01f * v[j];
        }
        *(float4*)(out + (size_t)grow * 128 + tx * 8)     = make_float4(v[0], v[1], v[2], v[3]);
        *(float4*)(out + (size_t)grow * 128 + tx * 8 + 4) = make_float4(v[4], v[5], v[6], v[7]);
    }
}

// ---------------- pool: batch sorted -> binary search segment, no atomics ----------------
__global__ void k_pool(const float* __restrict__ hin, const int* __restrict__ batch,
                       float* __restrict__ pooled, int n) {
    int g = blockIdx.x;
    int lo = 0, hi = n;
    while (lo < hi) { int m = (lo + hi) >> 1; if (batch[m] < g) lo = m + 1; else hi = m; }
    int start = lo;
    hi = n;
    while (lo < hi) { int m = (lo + hi) >> 1; if (batch[m] < g + 1) lo = m + 1; else hi = m; }
    int end = lo;
    int f = threadIdx.x;
    float acc = 0.f;
    for (int i = start; i < end; ++i) acc += hin[(size_t)i * 128 + f];
    pooled[g * 128 + f] = acc;
}

// ---------------- final: out = l2norm(leaky(pooled @ fc3^T + b)) ----------------
__global__ void k_final(const float* __restrict__ pooled, const float* __restrict__ W,
                        const float* __restrict__ b, float* __restrict__ outp) {
    __shared__ float pr[128];
    __shared__ float red[128];
    int g = blockIdx.x, hh = threadIdx.x;
    pr[hh] = pooled[g * 128 + hh];
    __syncthreads();
    float acc = b[hh];
#pragma unroll 8
    for (int k = 0; k < 128; ++k) acc += pr[k] * __ldg(&W[hh * 128 + k]);
    acc = (acc >= 0.f) ? acc : 0.01f * acc;
    red[hh] = acc * acc;
    __syncthreads();
    for (int s = 64; s > 0; s >>= 1) {
        if (hh < s) red[hh] += red[hh + s];
        __syncthreads();
    }
    float inv = 1.f / fmaxf(sqrtf(red[0]), 1e-12f);
    outp[g * 128 + hh] = acc * inv;
}

// ---------------- launcher ----------------
extern "C" void kernel_launch(void* const* d_in, const int* in_sizes, int n_in,
                              void* d_out, int out_size) {
    const float* x        = (const float*)d_in[0];
    const void*  eidx_raw = d_in[1];
    const void*  batch_raw= d_in[2];
    const float* W1l  = (const float*)d_in[3];
    const float* W1r  = (const float*)d_in[4];
    const float* W2l  = (const float*)d_in[5];
    const float* W2r  = (const float*)d_in[6];
    const float* fc1W = (const float*)d_in[7];
    const float* fc1b = (const float*)d_in[8];
    const float* fc2W = (const float*)d_in[9];
    const float* fc2b = (const float*)d_in[10];
    const float* fc3W = (const float*)d_in[11];
    const float* fc3b = (const float*)d_in[12];
    float* out = (float*)d_out;

    int n = in_sizes[0] / 128;
    int E = in_sizes[1] / 2;

    float *xn, *mean, *tb, *h1, *h, *pooled;
    int *rowptr, *fill, *col, *srcA, *dstA, *batch32, *is64;
    cudaGetSymbolAddress((void**)&xn,      g_xn);
    cudaGetSymbolAddress((void**)&mean,    g_mean);
    cudaGetSymbolAddress((void**)&tb,      g_t);
    cudaGetSymbolAddress((void**)&h1,      g_h1);
    cudaGetSymbolAddress((void**)&h,       g_h);
    cudaGetSymbolAddress((void**)&pooled,  g_pooled);
    cudaGetSymbolAddress((void**)&rowptr,  g_rowptr);
    cudaGetSymbolAddress((void**)&fill,    g_fill);
    cudaGetSymbolAddress((void**)&col,     g_col);
    cudaGetSymbolAddress((void**)&srcA,    g_src);
    cudaGetSymbolAddress((void**)&dstA,    g_dst);
    cudaGetSymbolAddress((void**)&batch32, g_batch);
    cudaGetSymbolAddress((void**)&is64,    g_is64);

    int smem = (256 * WS_LD + 16 * 128) * (int)sizeof(float);
    cudaFuncSetAttribute(k_gemm_dual, cudaFuncAttributeMaxDynamicSharedMemorySize, smem);

    int warpBlocks = (n * 32 + 255) / 256;
    int edgeBlocks = (E + 255) / 256;
    int gemmBlocks = (n + 127) / 128;
    int intBlocks  = (n + 255) / 256;

    // dtype probe + index conversion (graph-safe, deterministic)
    k_detect64<<<1, 256>>>(eidx_raw, 2 * E, n, is64);
    k_convert_edges<<<edgeBlocks, 256>>>(eidx_raw, E, is64, srcA, dstA);
    k_convert_batch<<<intBlocks, 256>>>(batch_raw, n, is64, batch32);

    // preprocess
    k_preprocess<<<warpBlocks, 256>>>(x, xn, n);

    // CSR build
    k_zero_int<<<intBlocks, 256>>>(fill, n);
    k_count_deg<<<edgeBlocks, 256>>>(dstA, fill, E);
    k_scan_deg<<<1, 1024>>>(fill, rowptr, n);
    k_copy_int<<<intBlocks, 256>>>(rowptr, fill, n);
    k_fill_edges<<<edgeBlocks, 256>>>(srcA, dstA, fill, col, E);

    // conv1: t = mean1 @ W1l^T + xn @ W1r^T ; h1 = leaky(l2norm(t))
    k_aggregate<<<warpBlocks, 256>>>(xn, rowptr, col, mean, n);
    k_gemm_dual<<<gemmBlocks, 256, smem>>>(mean, xn, W1l, W1r, 128, nullptr, tb, n, 0);
    k_normleaky<<<warpBlocks, 256>>>(tb, h1, n);

    // fc1: h = leaky([h1, xn] @ fc1W^T + b)
    k_gemm_dual<<<gemmBlocks, 256, smem>>>(h1, xn, fc1W, fc1W + 128, 256, fc1b, h, n, 1);

    // conv2 on h
    k_aggregate<<<warpBlocks, 256>>>(h, rowptr, col, mean, n);
    k_gemm_dual<<<gemmBlocks, 256, smem>>>(mean, h, W2l, W2r, 128, nullptr, tb, n, 0);
    k_normleaky<<<warpBlocks, 256>>>(tb, h1, n);

    // fc2: t = leaky([h2, h] @ fc2W^T + b)
    k_gemm_dual<<<gemmBlocks, 256, smem>>>(h1, h, fc2W, fc2W + 128, 256, fc2b, tb, n, 1);

    // pool + final
    k_pool<<<GMAX, 128>>>(tb, batch32, pooled, n);
    k_final<<<GMAX, 128>>>(pooled, fc3W, fc3b, out);
}

// round 5
// speedup vs baseline: 1.6053x; 1.6053x over previous
#include <cuda_runtime.h>
#include <cuda_bf16.h>
#include <math.h>
#include <stdint.h>

#define NMAX 50000
#define NPAD 50176      // 392 tiles * 128
#define EMAX 600000
#define GMAX 128

// ---------------- scratch ----------------
__device__ __align__(16) float g_xn[NPAD * 128];
__device__ __align__(16) float g_mean[NPAD * 128];
__device__ __align__(16) float g_t[NPAD * 128];
__device__ __align__(16) float g_h1[NPAD * 128];
__device__ __align__(16) float g_h[NPAD * 128];
__device__ __align__(16) float g_pooled[GMAX * 128];
__device__ int g_rowptr[NMAX + 1];
__device__ int g_fill[NMAX];
__device__ int g_col[EMAX];
__device__ int g_src[EMAX];
__device__ int g_dst[EMAX];
__device__ int g_batch[NMAX];
__device__ int g_is64;

// ---------------- tf32 helpers ----------------
__device__ __forceinline__ uint32_t f2tf32(float f) {
    uint32_t r;
    asm("cvt.rna.tf32.f32 %0, %1;" : "=r"(r) : "f"(f));
    return r;
}
__device__ __forceinline__ void mma_tf32_16n8k8(float* d, const uint32_t* a, const uint32_t* b) {
    asm volatile(
        "mma.sync.aligned.m16n8k8.row.col.f32.tf32.tf32.f32 "
        "{%0,%1,%2,%3}, {%4,%5,%6,%7}, {%8,%9}, {%0,%1,%2,%3};"
        : "+f"(d[0]), "+f"(d[1]), "+f"(d[2]), "+f"(d[3])
        : "r"(a[0]), "r"(a[1]), "r"(a[2]), "r"(a[3]), "r"(b[0]), "r"(b[1]));
}

// ---------------- dtype probe + conversion ----------------
__global__ void k_detect64(const void* raw, int count, int nlimit, int* flag) {
    __shared__ int ok;
    if (threadIdx.x == 0) ok = 1;
    __syncthreads();
    int m = count / 2 < 1024 ? count / 2 : 1024;
    const long long* p = (const long long*)raw;
    for (int i = threadIdx.x; i < m; i += blockDim.x) {
        long long v = p[i];
        if (v < 0 || v >= (long long)nlimit) ok = 0;
    }
    __syncthreads();
    if (threadIdx.x == 0) *flag = ok;
}

__global__ void k_convert_count(const void* raw, int E, const int* flag,
                                int* __restrict__ src, int* __restrict__ dst,
                                int* __restrict__ deg) {
    int e = blockIdx.x * blockDim.x + threadIdx.x;
    if (e >= E) return;
    int s, d;
    if (*flag) {
        const long long* p = (const long long*)raw;
        s = (int)p[e]; d = (int)p[E + e];
    } else {
        const int* p = (const int*)raw;
        s = p[e]; d = p[E + e];
    }
    src[e] = s; dst[e] = d;
    atomicAdd(&deg[d], 1);
}

__global__ void k_convert_batch(const void* raw, int n, const int* flag, int* __restrict__ b) {
    int i = blockIdx.x * blockDim.x + threadIdx.x;
    if (i >= n) return;
    if (*flag) b[i] = (int)((const long long*)raw)[i];
    else       b[i] = ((const int*)raw)[i];
}

__global__ void k_zero_int(int* __restrict__ p, int n) {
    int i = blockIdx.x * blockDim.x + threadIdx.x;
    if (i < n) p[i] = 0;
}
__global__ void k_copy_int(const int* __restrict__ s, int* __restrict__ d, int n) {
    int i = blockIdx.x * blockDim.x + threadIdx.x;
    if (i < n) d[i] = s[i];
}

// ---------------- preprocess ----------------
__global__ void k_preprocess(const float* __restrict__ x, float* __restrict__ xn, int n) {
    int w = (blockIdx.x * blockDim.x + threadIdx.x) >> 5;
    if (w >= n) return;
    int lane = threadIdx.x & 31;
    float4 v = *(const float4*)(x + (size_t)w * 128 + lane * 4);
    float s = v.x + v.y + v.z + v.w;
#pragma unroll
    for (int o = 16; o > 0; o >>= 1) s += __shfl_xor_sync(0xffffffffu, s, o);
    float rinv = (s != 0.f) ? (1.f / s) : 0.f;
    *(float4*)(xn + (size_t)w * 128 + lane * 4) = make_float4(v.x * rinv, v.y * rinv, v.z * rinv, v.w * rinv);
}

// ---------------- CSR scan / fill ----------------
__global__ void k_scan_deg(const int* __restrict__ deg, int* __restrict__ rowptr, int n) {
    __shared__ int wsum[32];
    __shared__ int s_total;
    int t = threadIdx.x, lane = t & 31, wid = t >> 5;
    int carry = 0;
    for (int base = 0; base < n; base += 1024) {
        int v = (base + t < n) ? deg[base + t] : 0;
        int xv = v;
#pragma unroll
        for (int o = 1; o < 32; o <<= 1) {
            int y = __shfl_up_sync(0xffffffffu, xv, o);
            if (lane >= o) xv += y;
        }
        if (lane == 31) wsum[wid] = xv;
        __syncthreads();
        if (wid == 0) {
            int wv = wsum[lane];
#pragma unroll
            for (int o = 1; o < 32; o <<= 1) {
                int y = __shfl_up_sync(0xffffffffu, wv, o);
                if (lane >= o) wv += y;
            }
            wsum[lane] = wv;
            if (lane == 31) s_total = wv;
        }
        __syncthreads();
        int incl = xv + (wid > 0 ? wsum[wid - 1] : 0);
        if (base + t < n) rowptr[base + t] = carry + incl - v;
        carry += s_total;
        __syncthreads();
    }
    if (t == 0) rowptr[n] = carry;
}

__global__ void k_fill_edges(const int* __restrict__ src, const int* __restrict__ dst,
                             int* __restrict__ fillc, int* __restrict__ col, int E) {
    int e = blockIdx.x * blockDim.x + threadIdx.x;
    if (e < E) {
        int p = atomicAdd(&fillc[dst[e]], 1);
        col[p] = src[e];
    }
}

// ---------------- mean aggregation ----------------
__global__ void k_aggregate(const float* __restrict__ xin, const int* __restrict__ rowptr,
                            const int* __restrict__ col, float* __restrict__ outm, int n) {
    int w = (blockIdx.x * blockDim.x + threadIdx.x) >> 5;
    if (w >= n) return;
    int lane = threadIdx.x & 31;
    int s0 = rowptr[w], s1 = rowptr[w + 1];
    float ax = 0.f, ay = 0.f, az = 0.f, aw = 0.f;
    for (int j = s0; j < s1; ++j) {
        int s = __ldg(&col[j]);
        float4 v = *(const float4*)(xin + (size_t)s * 128 + lane * 4);
        ax += v.x; ay += v.y; az += v.z; aw += v.w;
    }
    float inv = 1.f / fmaxf((float)(s1 - s0), 1.f);
    *(float4*)(outm + (size_t)w * 128 + lane * 4) = make_float4(ax * inv, ay * inv, az * inv, aw * inv);
}

// ---------------- mma.sync tf32 dual GEMM ----------------
// out = leaky( maybe_l2norm(A0@Wa^T + A1@Wb^T) + bias )
// Block: 256 thr (8 warps: 2M x 4N), tile 128x128, K=256.
// SMEM floats: Ws [256][136] | As0 [128][20] | As1 [128][20] | bias[128] | rowss[128]
#define WS_STRIDE 136
#define AS_STRIDE 20
#define SM_WS     0
#define SM_AS0    (256 * WS_STRIDE)
#define SM_AS1    (SM_AS0 + 128 * AS_STRIDE)
#define SM_BS     (SM_AS1 + 128 * AS_STRIDE)
#define SM_RSS    (SM_BS + 128)
#define SM_FLOATS (SM_RSS + 128)
#define FLAG_LEAKY 1
#define FLAG_NORM  2

__global__ void __launch_bounds__(256, 1)
k_gemm_mma(const float* __restrict__ A0, const float* __restrict__ A1,
           const float* __restrict__ Wa, const float* __restrict__ Wb, int ldw,
           const float* __restrict__ bias, float* __restrict__ out, int n, int flags) {
    extern __shared__ float sm[];
    float* Ws    = sm + SM_WS;
    float* bs    = sm + SM_BS;
    float* rowss = sm + SM_RSS;

    int tid = threadIdx.x, lane = tid & 31, wid = tid >> 5;
    int wm = wid >> 2, wn = wid & 3;        // warp M (0..1), warp N (0..3)
    int lr = lane >> 2, lc = lane & 3;      // fragment row / col group

    if (tid < 128) bs[tid] = bias ? bias[tid] : 0.f;

    // Load weights k-major, converted to tf32: Ws[k][n]
    for (int idx = tid; idx < 128 * 128; idx += 256) {
        int nn = idx >> 7, k = idx & 127;
        Ws[k * WS_STRIDE + nn]         = __uint_as_float(f2tf32(Wa[(size_t)nn * ldw + k]));
        Ws[(128 + k) * WS_STRIDE + nn] = __uint_as_float(f2tf32(Wb[(size_t)nn * ldw + k]));
    }
    __syncthreads();

    int numTiles = (n + 127) >> 7;

    for (int tile = blockIdx.x; tile < numTiles; tile += gridDim.x) {
        int row0 = tile << 7;
        float acc[4][4][4];
#pragma unroll
        for (int i = 0; i < 4; ++i)
#pragma unroll
            for (int j = 0; j < 4; ++j)
#pragma unroll
                for (int q = 0; q < 4; ++q) acc[i][j][q] = 0.f;

        // preload chunk 0 (A0 cols 0..15) and stage into As0
        float4 rg[2];
        {
            const float* src = A0;
#pragma unroll
            for (int j = 0; j < 2; ++j) {
                int fi = tid * 2 + j;
                int r = fi >> 2, seg = fi & 3;
                float4 v = *(const float4*)(src + (size_t)(row0 + r) * 128 + seg * 4);
                rg[j].x = __uint_as_float(f2tf32(v.x));
                rg[j].y = __uint_as_float(f2tf32(v.y));
                rg[j].z = __uint_as_float(f2tf32(v.z));
                rg[j].w = __uint_as_float(f2tf32(v.w));
            }
            float* As = sm + SM_AS0;
#pragma unroll
            for (int j = 0; j < 2; ++j) {
                int fi = tid * 2 + j;
                int r = fi >> 2, seg = fi & 3;
                As[r * AS_STRIDE + seg * 4 + 0] = rg[j].x;
                As[r * AS_STRIDE + seg * 4 + 1] = rg[j].y;
                As[r * AS_STRIDE + seg * 4 + 2] = rg[j].z;
                As[r * AS_STRIDE + seg * 4 + 3] = rg[j].w;
            }
        }
        __syncthreads();

        for (int c = 0; c < 16; ++c) {
            const float* Asc = sm + ((c & 1) ? SM_AS1 : SM_AS0);
            // prefetch next chunk to regs
            if (c < 15) {
                int cn = c + 1;
                const float* src = (cn < 8) ? A0 : A1;
                int colb = (cn & 7) * 16;
#pragma unroll
                for (int j = 0; j < 2; ++j) {
                    int fi = tid * 2 + j;
                    int r = fi >> 2, seg = fi & 3;
                    float4 v = *(const float4*)(src + (size_t)(row0 + r) * 128 + colb + seg * 4);
                    rg[j].x = __uint_as_float(f2tf32(v.x));
                    rg[j].y = __uint_as_float(f2tf32(v.y));
                    rg[j].z = __uint_as_float(f2tf32(v.z));
                    rg[j].w = __uint_as_float(f2tf32(v.w));
                }
            }
            // compute 2 x k8 on this chunk
#pragma unroll
            for (int h = 0; h < 2; ++h) {
                int k8 = h * 8;
                int kk = c * 16 + k8;
                uint32_t a[4][4], b[4][2];
#pragma unroll
                for (int i = 0; i < 4; ++i) {
                    int m0 = wm * 64 + i * 16;
                    const float* base = Asc + (m0 + lr) * AS_STRIDE + k8 + lc;
                    a[i][0] = __float_as_uint(base[0]);
                    a[i][1] = __float_as_uint(base[8 * AS_STRIDE]);
                    a[i][2] = __float_as_uint(base[4]);
                    a[i][3] = __float_as_uint(base[8 * AS_STRIDE + 4]);
                }
#pragma unroll
                for (int j = 0; j < 4; ++j) {
                    int n0 = wn * 32 + j * 8;
                    const float* base = Ws + (kk + lc) * WS_STRIDE + n0 + lr;
                    b[j][0] = __float_as_uint(base[0]);
                    b[j][1] = __float_as_uint(base[4 * WS_STRIDE]);
                }
#pragma unroll
                for (int i = 0; i < 4; ++i)
#pragma unroll
                    for (int j = 0; j < 4; ++j)
                        mma_tf32_16n8k8(acc[i][j], a[i], b[j]);
            }
            // stage next chunk
            if (c < 15) {
                float* As = sm + (((c + 1) & 1) ? SM_AS1 : SM_AS0);
#pragma unroll
                for (int j = 0; j < 2; ++j) {
                    int fi = tid * 2 + j;
                    int r = fi >> 2, seg = fi & 3;
                    As[r * AS_STRIDE + seg * 4 + 0] = rg[j].x;
                    As[r * AS_STRIDE + seg * 4 + 1] = rg[j].y;
                    As[r * AS_STRIDE + seg * 4 + 2] = rg[j].z;
                    As[r * AS_STRIDE + seg * 4 + 3] = rg[j].w;
                }
            }
            __syncthreads();
        }

        // ---------------- epilogue ----------------
        bool donorm = (flags & FLAG_NORM) != 0;
        if (donorm) {
            if (tid < 128) rowss[tid] = 0.f;
            __syncthreads();
#pragma unroll
            for (int i = 0; i < 4; ++i) {
#pragma unroll
                for (int rh = 0; rh < 2; ++rh) {
                    float ss = 0.f;
#pragma unroll
                    for (int j = 0; j < 4; ++j) {
                        float d0 = acc[i][j][rh * 2], d1 = acc[i][j][rh * 2 + 1];
                        ss += d0 * d0 + d1 * d1;
                    }
                    // reduce across the 4 lanes of the quad (same row)
                    ss += __shfl_xor_sync(0xffffffffu, ss, 1);
                    ss += __shfl_xor_sync(0xffffffffu, ss, 2);
                    if (lc == 0) {
                        int rl = wm * 64 + i * 16 + lr + rh * 8;
                        atomicAdd(&rowss[rl], ss);
                    }
                }
            }
            __syncthreads();
        }
#pragma unroll
        for (int i = 0; i < 4; ++i) {
#pragma unroll
            for (int rh = 0; rh < 2; ++rh) {
                int rl = wm * 64 + i * 16 + lr + rh * 8;
                int row = row0 + rl;
                if (row >= n) continue;
                float inv = 1.f;
                if (donorm) inv = 1.f / fmaxf(sqrtf(rowss[rl]), 1e-12f);
#pragma unroll
                for (int j = 0; j < 4; ++j) {
                    int colp = wn * 32 + j * 8 + 2 * lc;
                    float v0 = acc[i][j][rh * 2] * inv + bs[colp];
                    float v1 = acc[i][j][rh * 2 + 1] * inv + bs[colp + 1];
                    v0 = (v0 >= 0.f) ? v0 : 0.01f * v0;
                    v1 = (v1 >= 0.f) ? v1 : 0.01f * v1;
                    *(float2*)(out + (size_t)row * 128 + colp) = make_float2(v0, v1);
                }
            }
        }
        __syncthreads();
    }
}

// ---------------- pool + final ----------------
__global__ void k_pool(const float* __restrict__ hin, const int* __restrict__ batch,
                       float* __restrict__ pooled, int n) {
    int g = blockIdx.x;
    int lo = 0, hi = n;
    while (lo < hi) { int m = (lo + hi) >> 1; if (batch[m] < g) lo = m + 1; else hi = m; }
    int start = lo;
    hi = n;
    while (lo < hi) { int m = (lo + hi) >> 1; if (batch[m] < g + 1) lo = m + 1; else hi = m; }
    int end = lo;
    int f = threadIdx.x;
    float acc = 0.f;
    for (int i = start; i < end; ++i) acc += hin[(size_t)i * 128 + f];
    pooled[g * 128 + f] = acc;
}

__global__ void k_final(const float* __restrict__ pooled, const float* __restrict__ W,
                        const float* __restrict__ b, float* __restrict__ outp) {
    __shared__ float pr[128];
    __shared__ float red[128];
    int g = blockIdx.x, hh = threadIdx.x;
    pr[hh] = pooled[g * 128 + hh];
    __syncthreads();
    float acc = b[hh];
#pragma unroll 8
    for (int k = 0; k < 128; ++k) acc += pr[k] * __ldg(&W[hh * 128 + k]);
    acc = (acc >= 0.f) ? acc : 0.01f * acc;
    red[hh] = acc * acc;
    __syncthreads();
    for (int s = 64; s > 0; s >>= 1) {
        if (hh < s) red[hh] += red[hh + s];
        __syncthreads();
    }
    float inv = 1.f / fmaxf(sqrtf(red[0]), 1e-12f);
    outp[g * 128 + hh] = acc * inv;
}

// ---------------- launcher ----------------
extern "C" void kernel_launch(void* const* d_in, const int* in_sizes, int n_in,
                              void* d_out, int out_size) {
    const float* x         = (const float*)d_in[0];
    const void*  eidx_raw  = d_in[1];
    const void*  batch_raw = d_in[2];
    const float* W1l  = (const float*)d_in[3];
    const float* W1r  = (const float*)d_in[4];
    const float* W2l  = (const float*)d_in[5];
    const float* W2r  = (const float*)d_in[6];
    const float* fc1W = (const float*)d_in[7];
    const float* fc1b = (const float*)d_in[8];
    const float* fc2W = (const float*)d_in[9];
    const float* fc2b = (const float*)d_in[10];
    const float* fc3W = (const float*)d_in[11];
    const float* fc3b = (const float*)d_in[12];
    float* out = (float*)d_out;

    int n = in_sizes[0] / 128;
    int E = in_sizes[1] / 2;

    float *xn, *mean, *tb, *h1, *h, *pooled;
    int *rowptr, *fill, *col, *srcA, *dstA, *batch32, *is64;
    cudaGetSymbolAddress((void**)&xn,      g_xn);
    cudaGetSymbolAddress((void**)&mean,    g_mean);
    cudaGetSymbolAddress((void**)&tb,      g_t);
    cudaGetSymbolAddress((void**)&h1,      g_h1);
    cudaGetSymbolAddress((void**)&h,       g_h);
    cudaGetSymbolAddress((void**)&pooled,  g_pooled);
    cudaGetSymbolAddress((void**)&rowptr,  g_rowptr);
    cudaGetSymbolAddress((void**)&fill,    g_fill);
    cudaGetSymbolAddress((void**)&col,     g_col);
    cudaGetSymbolAddress((void**)&srcA,    g_src);
    cudaGetSymbolAddress((void**)&dstA,    g_dst);
    cudaGetSymbolAddress((void**)&batch32, g_batch);
    cudaGetSymbolAddress((void**)&is64,    g_is64);

    int smemB = SM_FLOATS * (int)sizeof(float);
    cudaFuncSetAttribute(k_gemm_mma, cudaFuncAttributeMaxDynamicSharedMemorySize, smemB);

    int warpBlocks = (n * 32 + 255) / 256;
    int edgeBlocks = (E + 255) / 256;
    int intBlocks  = (n + 255) / 256;
    int gemmGrid   = 148;

    // dtype probe + fused convert/count
    k_detect64<<<1, 256>>>(eidx_raw, 2 * E, n, is64);
    k_zero_int<<<intBlocks, 256>>>(fill, n);
    k_convert_count<<<edgeBlocks, 256>>>(eidx_raw, E, is64, srcA, dstA, fill);
    k_convert_batch<<<intBlocks, 256>>>(batch_raw, n, is64, batch32);

    // preprocess
    k_preprocess<<<warpBlocks, 256>>>(x, xn, n);

    // CSR
    k_scan_deg<<<1, 1024>>>(fill, rowptr, n);
    k_copy_int<<<intBlocks, 256>>>(rowptr, fill, n);
    k_fill_edges<<<edgeBlocks, 256>>>(srcA, dstA, fill, col, E);

    // conv1: h1 = leaky(l2norm(mean@W1l^T + xn@W1r^T))
    k_aggregate<<<warpBlocks, 256>>>(xn, rowptr, col, mean, n);
    k_gemm_mma<<<gemmGrid, 256, smemB>>>(mean, xn, W1l, W1r, 128, nullptr, h1, n, FLAG_LEAKY | FLAG_NORM);

    // fc1: h = leaky([h1|xn]@fc1W^T + b)
    k_gemm_mma<<<gemmGrid, 256, smemB>>>(h1, xn, fc1W, fc1W + 128, 256, fc1b, h, n, FLAG_LEAKY);

    // conv2: h1 = leaky(l2norm(mean@W2l^T + h@W2r^T))
    k_aggregate<<<warpBlocks, 256>>>(h, rowptr, col, mean, n);
    k_gemm_mma<<<gemmGrid, 256, smemB>>>(mean, h, W2l, W2r, 128, nullptr, h1, n, FLAG_LEAKY | FLAG_NORM);

    // fc2: tb = leaky([h1|h]@fc2W^T + b)
    k_gemm_mma<<<gemmGrid, 256, smemB>>>(h1, h, fc2W, fc2W + 128, 256, fc2b, tb, n, FLAG_LEAKY);

    // pool + final
    k_pool<<<GMAX, 128>>>(tb, batch32, pooled, n);
    k_final<<<GMAX, 128>>>(pooled, fc3W, fc3b, out);
}

// round 6
// speedup vs baseline: 1.8565x; 1.1565x over previous
#include <cuda_runtime.h>
#include <cuda_bf16.h>
#include <math.h>
#include <stdint.h>

#define NMAX 50000
#define NPAD 50176      // 392 tiles * 128
#define EMAX 600000
#define GMAX 128

// ---------------- scratch ----------------
__device__ __align__(16) float g_xn[NPAD * 128];
__device__ __align__(16) float g_mean[NPAD * 128];
__device__ __align__(16) float g_t[NPAD * 128];
__device__ __align__(16) float g_h1[NPAD * 128];
__device__ __align__(16) float g_h[NPAD * 128];
__device__ __align__(16) float g_pooled[GMAX * 128];
__device__ int g_rowptr[NMAX + 1];
__device__ int g_fill[NMAX];
__device__ int g_col[EMAX];
__device__ int g_src[EMAX];
__device__ int g_dst[EMAX];
__device__ int g_batch[NMAX];
__device__ int g_is64;

// ---------------- tf32 helpers ----------------
__device__ __forceinline__ uint32_t f2tf32(float f) {
    uint32_t r;
    asm("cvt.rna.tf32.f32 %0, %1;" : "=r"(r) : "f"(f));
    return r;
}
__device__ __forceinline__ void mma_tf32_16n8k8(float* d, const uint32_t* a, const uint32_t* b) {
    asm volatile(
        "mma.sync.aligned.m16n8k8.row.col.f32.tf32.tf32.f32 "
        "{%0,%1,%2,%3}, {%4,%5,%6,%7}, {%8,%9}, {%0,%1,%2,%3};"
        : "+f"(d[0]), "+f"(d[1]), "+f"(d[2]), "+f"(d[3])
        : "r"(a[0]), "r"(a[1]), "r"(a[2]), "r"(a[3]), "r"(b[0]), "r"(b[1]));
}
__device__ __forceinline__ int swz(int g) { return g ^ (g >> 3); }  // 32-granule xor swizzle

// ---------------- dtype probe + conversion ----------------
__global__ void k_detect64(const void* raw, int count, int nlimit, int* flag) {
    __shared__ int ok;
    if (threadIdx.x == 0) ok = 1;
    __syncthreads();
    int m = count / 2 < 1024 ? count / 2 : 1024;
    const long long* p = (const long long*)raw;
    for (int i = threadIdx.x; i < m; i += blockDim.x) {
        long long v = p[i];
        if (v < 0 || v >= (long long)nlimit) ok = 0;
    }
    __syncthreads();
    if (threadIdx.x == 0) *flag = ok;
}

__global__ void k_convert_count(const void* raw, int E, const int* flag,
                                int* __restrict__ src, int* __restrict__ dst,
                                int* __restrict__ deg) {
    int e = blockIdx.x * blockDim.x + threadIdx.x;
    if (e >= E) return;
    int s, d;
    if (*flag) {
        const long long* p = (const long long*)raw;
        s = (int)p[e]; d = (int)p[E + e];
    } else {
        const int* p = (const int*)raw;
        s = p[e]; d = p[E + e];
    }
    src[e] = s; dst[e] = d;
    atomicAdd(&deg[d], 1);
}

__global__ void k_convert_batch(const void* raw, int n, const int* flag, int* __restrict__ b) {
    int i = blockIdx.x * blockDim.x + threadIdx.x;
    if (i >= n) return;
    if (*flag) b[i] = (int)((const long long*)raw)[i];
    else       b[i] = ((const int*)raw)[i];
}

__global__ void k_zero_int(int* __restrict__ p, int n) {
    int i = blockIdx.x * blockDim.x + threadIdx.x;
    if (i < n) p[i] = 0;
}

// ---------------- preprocess ----------------
__global__ void k_preprocess(const float* __restrict__ x, float* __restrict__ xn, int n) {
    int w = (blockIdx.x * blockDim.x + threadIdx.x) >> 5;
    if (w >= n) return;
    int lane = threadIdx.x & 31;
    float4 v = *(const float4*)(x + (size_t)w * 128 + lane * 4);
    float s = v.x + v.y + v.z + v.w;
#pragma unroll
    for (int o = 16; o > 0; o >>= 1) s += __shfl_xor_sync(0xffffffffu, s, o);
    float rinv = (s != 0.f) ? (1.f / s) : 0.f;
    *(float4*)(xn + (size_t)w * 128 + lane * 4) = make_float4(v.x * rinv, v.y * rinv, v.z * rinv, v.w * rinv);
}

// ---------------- CSR scan (also seeds fill cursor in-place) ----------------
__global__ void k_scan_deg(int* __restrict__ deg_fill, int* __restrict__ rowptr, int n) {
    __shared__ int wsum[32];
    __shared__ int s_total;
    int t = threadIdx.x, lane = t & 31, wid = t >> 5;
    int carry = 0;
    for (int base = 0; base < n; base += 1024) {
        int v = (base + t < n) ? deg_fill[base + t] : 0;
        int xv = v;
#pragma unroll
        for (int o = 1; o < 32; o <<= 1) {
            int y = __shfl_up_sync(0xffffffffu, xv, o);
            if (lane >= o) xv += y;
        }
        if (lane == 31) wsum[wid] = xv;
        __syncthreads();
        if (wid == 0) {
            int wv = wsum[lane];
#pragma unroll
            for (int o = 1; o < 32; o <<= 1) {
                int y = __shfl_up_sync(0xffffffffu, wv, o);
                if (lane >= o) wv += y;
            }
            wsum[lane] = wv;
            if (lane == 31) s_total = wv;
        }
        __syncthreads();
        int excl = carry + xv + (wid > 0 ? wsum[wid - 1] : 0) - v;
        if (base + t < n) { rowptr[base + t] = excl; deg_fill[base + t] = excl; }
        carry += s_total;
        __syncthreads();
    }
    if (t == 0) rowptr[n] = carry;
}

__global__ void k_fill_edges(const int* __restrict__ src, const int* __restrict__ dst,
                             int* __restrict__ fillc, int* __restrict__ col, int E) {
    int e = blockIdx.x * blockDim.x + threadIdx.x;
    if (e < E) {
        int p = atomicAdd(&fillc[dst[e]], 1);
        col[p] = src[e];
    }
}

// ---------------- mean aggregation ----------------
__global__ void k_aggregate(const float* __restrict__ xin, const int* __restrict__ rowptr,
                            const int* __restrict__ col, float* __restrict__ outm, int n) {
    int w = (blockIdx.x * blockDim.x + threadIdx.x) >> 5;
    if (w >= n) return;
    int lane = threadIdx.x & 31;
    int s0 = rowptr[w], s1 = rowptr[w + 1];
    float ax = 0.f, ay = 0.f, az = 0.f, aw = 0.f;
    for (int j = s0; j < s1; ++j) {
        int s = __ldg(&col[j]);
        float4 v = *(const float4*)(xin + (size_t)s * 128 + lane * 4);
        ax += v.x; ay += v.y; az += v.z; aw += v.w;
    }
    float inv = 1.f / fmaxf((float)(s1 - s0), 1.f);
    *(float4*)(outm + (size_t)w * 128 + lane * 4) = make_float4(ax * inv, ay * inv, az * inv, aw * inv);
}

// ---------------- mma.sync tf32 dual GEMM, fragment-order SMEM ----------------
// out = leaky( maybe_l2norm(A0@Wa^T + A1@Wb^T) + bias )
// Block 256 thr (8 warps: 2M x 4N), tile 128x128, K=256.
// Wf: [32 k8][16 nt] x 64 floats (fragment order)         = 32768 floats
// Af: 2 bufs x [2 k8][8 mt] x 128 floats (fragment order) =  4096 floats
#define SM_WF     0
#define SM_AF0    32768
#define SM_AF1    (SM_AF0 + 2048)
#define SM_BS     (SM_AF1 + 2048)
#define SM_RSS    (SM_BS + 128)
#define SM_FLOATS (SM_RSS + 128)
#define FLAG_LEAKY 1
#define FLAG_NORM  2

__global__ void __launch_bounds__(256, 1)
k_gemm_mma(const float* __restrict__ A0, const float* __restrict__ A1,
           const float* __restrict__ Wa, const float* __restrict__ Wb, int ldw,
           const float* __restrict__ bias, float* __restrict__ out, int n, int flags) {
    extern __shared__ float sm[];
    float* Wf    = sm + SM_WF;
    float* bs    = sm + SM_BS;
    float* rowss = sm + SM_RSS;

    int tid = threadIdx.x, lane = tid & 31, wid = tid >> 5;
    int wm = wid >> 2, wn = wid & 3;

    if (tid < 128) bs[tid] = bias ? bias[tid] : 0.f;

    // ---- stage weights into fragment order (once per CTA) ----
    // element W[nn][k] -> Wf[(k>>3)*16 + (nn>>3)]*64 + ((nn&7)*4 + (k&3 of k&7))*2 + ((k&7)>>2)
    for (int it = 0; it < 32; ++it) {
        int idx4 = it * 256 + tid;             // 8192 float4 total
        int nn = idx4 >> 6;                     // 64 float4 per 256-wide row
        int k4 = (idx4 & 63) * 4;
        float4 v = (k4 < 128) ? *(const float4*)(Wa + (size_t)nn * ldw + k4)
                              : *(const float4*)(Wb + (size_t)nn * ldw + (k4 - 128));
        float vv[4] = {v.x, v.y, v.z, v.w};
#pragma unroll
        for (int q = 0; q < 4; ++q) {
            int k = k4 + q;
            int kb = k >> 3, kc = k & 7, nt = nn >> 3, nl = nn & 7;
            Wf[(kb * 16 + nt) * 64 + (nl * 4 + (kc & 3)) * 2 + (kc >> 2)] = __uint_as_float(f2tf32(vv[q]));
        }
    }
    __syncthreads();

    int numTiles = (n + 127) >> 7;
    int r = tid >> 1, ch = tid & 1;
    int mt_s = r >> 4, lrr = r & 7, rh = (r >> 3) & 1;

    for (int tile = blockIdx.x; tile < numTiles; tile += gridDim.x) {
        int row0 = tile << 7;
        float acc[4][4][4];
#pragma unroll
        for (int i = 0; i < 4; ++i)
#pragma unroll
            for (int j = 0; j < 4; ++j)
#pragma unroll
                for (int q = 0; q < 4; ++q) acc[i][j][q] = 0.f;

        // preload chunk 0 into Af0
        {
            const float* srcp = A0;
            int colb = ch * 8;
            float4 v0 = *(const float4*)(srcp + (size_t)(row0 + r) * 128 + colb);
            float4 v1 = *(const float4*)(srcp + (size_t)(row0 + r) * 128 + colb + 4);
            float vv[8] = {v0.x, v0.y, v0.z, v0.w, v1.x, v1.y, v1.z, v1.w};
            float* blk = sm + SM_AF0 + (ch * 8 + mt_s) * 128;
#pragma unroll
            for (int q = 0; q < 8; ++q) {
                int g = lrr * 4 + (q & 3);
                blk[swz(g) * 4 + rh + 2 * (q >> 2)] = __uint_as_float(f2tf32(vv[q]));
            }
        }
        __syncthreads();

        for (int c = 0; c < 16; ++c) {
            // prefetch next chunk to regs
            float vv[8];
            if (c < 15) {
                int cn = c + 1;
                const float* srcp = (cn < 8) ? A0 : A1;
                int colb = (cn & 7) * 16 + ch * 8;
                float4 v0 = *(const float4*)(srcp + (size_t)(row0 + r) * 128 + colb);
                float4 v1 = *(const float4*)(srcp + (size_t)(row0 + r) * 128 + colb + 4);
                vv[0] = v0.x; vv[1] = v0.y; vv[2] = v0.z; vv[3] = v0.w;
                vv[4] = v1.x; vv[5] = v1.y; vv[6] = v1.z; vv[7] = v1.w;
            }
            const float* Ab = sm + ((c & 1) ? SM_AF1 : SM_AF0);
#pragma unroll
            for (int h = 0; h < 2; ++h) {
                int kb = c * 2 + h;
                uint32_t a[4][4], b[4][2];
#pragma unroll
                for (int i = 0; i < 4; ++i) {
                    float4 af = *(const float4*)(Ab + (h * 8 + wm * 4 + i) * 128 + swz(lane) * 4);
                    a[i][0] = __float_as_uint(af.x);
                    a[i][1] = __float_as_uint(af.y);
                    a[i][2] = __float_as_uint(af.z);
                    a[i][3] = __float_as_uint(af.w);
                }
#pragma unroll
                for (int j = 0; j < 4; ++j) {
                    float2 bf = *(const float2*)(Wf + (kb * 16 + wn * 4 + j) * 64 + lane * 2);
                    b[j][0] = __float_as_uint(bf.x);
                    b[j][1] = __float_as_uint(bf.y);
                }
#pragma unroll
                for (int i = 0; i < 4; ++i)
#pragma unroll
                    for (int j = 0; j < 4; ++j)
                        mma_tf32_16n8k8(acc[i][j], a[i], b[j]);
            }
            // store prefetched chunk
            if (c < 15) {
                float* blk = sm + (((c + 1) & 1) ? SM_AF1 : SM_AF0) + (ch * 8 + mt_s) * 128;
#pragma unroll
                for (int q = 0; q < 8; ++q) {
                    int g = lrr * 4 + (q & 3);
                    blk[swz(g) * 4 + rh + 2 * (q >> 2)] = __uint_as_float(f2tf32(vv[q]));
                }
            }
            __syncthreads();
        }

        // ---------------- epilogue ----------------
        int lr = lane >> 2, lc = lane & 3;
        bool donorm = (flags & FLAG_NORM) != 0;
        if (donorm) {
            if (tid < 128) rowss[tid] = 0.f;
            __syncthreads();
#pragma unroll
            for (int i = 0; i < 4; ++i) {
#pragma unroll
                for (int rh2 = 0; rh2 < 2; ++rh2) {
                    float ss = 0.f;
#pragma unroll
                    for (int j = 0; j < 4; ++j) {
                        float d0 = acc[i][j][rh2 * 2], d1 = acc[i][j][rh2 * 2 + 1];
                        ss += d0 * d0 + d1 * d1;
                    }
                    ss += __shfl_xor_sync(0xffffffffu, ss, 1);
                    ss += __shfl_xor_sync(0xffffffffu, ss, 2);
                    if (lc == 0) atomicAdd(&rowss[wm * 64 + i * 16 + lr + rh2 * 8], ss);
                }
            }
            __syncthreads();
        }
#pragma unroll
        for (int i = 0; i < 4; ++i) {
#pragma unroll
            for (int rh2 = 0; rh2 < 2; ++rh2) {
                int rl = wm * 64 + i * 16 + lr + rh2 * 8;
                int row = row0 + rl;
                if (row >= n) continue;
                float inv = 1.f;
                if (donorm) inv = 1.f / fmaxf(sqrtf(rowss[rl]), 1e-12f);
#pragma unroll
                for (int j = 0; j < 4; ++j) {
                    int colp = wn * 32 + j * 8 + 2 * lc;
                    float v0 = acc[i][j][rh2 * 2] * inv + bs[colp];
                    float v1 = acc[i][j][rh2 * 2 + 1] * inv + bs[colp + 1];
                    v0 = (v0 >= 0.f) ? v0 : 0.01f * v0;
                    v1 = (v1 >= 0.f) ? v1 : 0.01f * v1;
                    *(float2*)(out + (size_t)row * 128 + colp) = make_float2(v0, v1);
                }
            }
        }
        __syncthreads();
    }
}

// ---------------- pool + final ----------------
__global__ void k_pool(const float* __restrict__ hin, const int* __restrict__ batch,
                       float* __restrict__ pooled, int n) {
    int g = blockIdx.x;
    int lo = 0, hi = n;
    while (lo < hi) { int m = (lo + hi) >> 1; if (batch[m] < g) lo = m + 1; else hi = m; }
    int start = lo;
    hi = n;
    while (lo < hi) { int m = (lo + hi) >> 1; if (batch[m] < g + 1) lo = m + 1; else hi = m; }
    int end = lo;
    int f = threadIdx.x;
    float acc = 0.f;
    for (int i = start; i < end; ++i) acc += hin[(size_t)i * 128 + f];
    pooled[g * 128 + f] = acc;
}

__global__ void k_final(const float* __restrict__ pooled, const float* __restrict__ W,
                        const float* __restrict__ b, float* __restrict__ outp) {
    __shared__ float pr[128];
    __shared__ float red[128];
    int g = blockIdx.x, hh = threadIdx.x;
    pr[hh] = pooled[g * 128 + hh];
    __syncthreads();
    float acc = b[hh];
#pragma unroll 8
    for (int k = 0; k < 128; ++k) acc += pr[k] * __ldg(&W[hh * 128 + k]);
    acc = (acc >= 0.f) ? acc : 0.01f * acc;
    red[hh] = acc * acc;
    __syncthreads();
    for (int s = 64; s > 0; s >>= 1) {
        if (hh < s) red[hh] += red[hh + s];
        __syncthreads();
    }
    float inv = 1.f / fmaxf(sqrtf(red[0]), 1e-12f);
    outp[g * 128 + hh] = acc * inv;
}

// ---------------- launcher ----------------
extern "C" void kernel_launch(void* const* d_in, const int* in_sizes, int n_in,
                              void* d_out, int out_size) {
    const float* x         = (const float*)d_in[0];
    const void*  eidx_raw  = d_in[1];
    const void*  batch_raw = d_in[2];
    const float* W1l  = (const float*)d_in[3];
    const float* W1r  = (const float*)d_in[4];
    const float* W2l  = (const float*)d_in[5];
    const float* W2r  = (const float*)d_in[6];
    const float* fc1W = (const float*)d_in[7];
    const float* fc1b = (const float*)d_in[8];
    const float* fc2W = (const float*)d_in[9];
    const float* fc2b = (const float*)d_in[10];
    const float* fc3W = (const float*)d_in[11];
    const float* fc3b = (const float*)d_in[12];
    float* out = (float*)d_out;

    int n = in_sizes[0] / 128;
    int E = in_sizes[1] / 2;

    float *xn, *mean, *tb, *h1, *h, *pooled;
    int *rowptr, *fill, *col, *srcA, *dstA, *batch32, *is64;
    cudaGetSymbolAddress((void**)&xn,      g_xn);
    cudaGetSymbolAddress((void**)&mean,    g_mean);
    cudaGetSymbolAddress((void**)&tb,      g_t);
    cudaGetSymbolAddress((void**)&h1,      g_h1);
    cudaGetSymbolAddress((void**)&h,       g_h);
    cudaGetSymbolAddress((void**)&pooled,  g_pooled);
    cudaGetSymbolAddress((void**)&rowptr,  g_rowptr);
    cudaGetSymbolAddress((void**)&fill,    g_fill);
    cudaGetSymbolAddress((void**)&col,     g_col);
    cudaGetSymbolAddress((void**)&srcA,    g_src);
    cudaGetSymbolAddress((void**)&dstA,    g_dst);
    cudaGetSymbolAddress((void**)&batch32, g_batch);
    cudaGetSymbolAddress((void**)&is64,    g_is64);

    int smemB = SM_FLOATS * (int)sizeof(float);
    cudaFuncSetAttribute(k_gemm_mma, cudaFuncAttributeMaxDynamicSharedMemorySize, smemB);

    int warpBlocks = (n * 32 + 255) / 256;
    int edgeBlocks = (E + 255) / 256;
    int intBlocks  = (n + 255) / 256;
    int gemmGrid   = 148;

    k_detect64<<<1, 256>>>(eidx_raw, 2 * E, n, is64);
    k_zero_int<<<intBlocks, 256>>>(fill, n);
    k_convert_count<<<edgeBlocks, 256>>>(eidx_raw, E, is64, srcA, dstA, fill);
    k_convert_batch<<<intBlocks, 256>>>(batch_raw, n, is64, batch32);

    k_preprocess<<<warpBlocks, 256>>>(x, xn, n);

    k_scan_deg<<<1, 1024>>>(fill, rowptr, n);   // writes rowptr AND resets fill to cursor
    k_fill_edges<<<edgeBlocks, 256>>>(srcA, dstA, fill, col, E);

    // conv1
    k_aggregate<<<warpBlocks, 256>>>(xn, rowptr, col, mean, n);
    k_gemm_mma<<<gemmGrid, 256, smemB>>>(mean, xn, W1l, W1r, 128, nullptr, h1, n, FLAG_LEAKY | FLAG_NORM);

    // fc1
    k_gemm_mma<<<gemmGrid, 256, smemB>>>(h1, xn, fc1W, fc1W + 128, 256, fc1b, h, n, FLAG_LEAKY);

    // conv2
    k_aggregate<<<warpBlocks, 256>>>(h, rowptr, col, mean, n);
    k_gemm_mma<<<gemmGrid, 256, smemB>>>(mean, h, W2l, W2r, 128, nullptr, h1, n, FLAG_LEAKY | FLAG_NORM);

    // fc2
    k_gemm_mma<<<gemmGrid, 256, smemB>>>(h1, h, fc2W, fc2W + 128, 256, fc2b, tb, n, FLAG_LEAKY);

    // pool + final
    k_pool<<<GMAX, 128>>>(tb, batch32, pooled, n);
    k_final<<<GMAX, 128>>>(pooled, fc3W, fc3b, out);
}

// round 7
// speedup vs baseline: 2.1172x; 1.1404x over previous
#include <cuda_runtime.h>
#include <cuda_bf16.h>
#include <math.h>
#include <stdint.h>

#define NMAX 50000
#define NPAD 50176      // 392 tiles * 128
#define EMAX 600000
#define GMAX 128

// ---------------- scratch ----------------
__device__ __align__(16) float g_xn[NPAD * 128];
__device__ __align__(16) float g_mean[NPAD * 128];
__device__ __align__(16) float g_t[NPAD * 128];
__device__ __align__(16) float g_h1[NPAD * 128];
__device__ __align__(16) float g_h[NPAD * 128];
__device__ __align__(16) float g_pooled[4 * GMAX * 128];
__device__ __align__(16) int g_rowptr[NMAX + 8];
__device__ __align__(16) int g_fill[NMAX + 8];
__device__ int g_col[EMAX];
__device__ int g_src[EMAX];
__device__ int g_dst[EMAX];
__device__ int g_batch[NMAX + 8];
__device__ int g_is64;

// ---------------- tf32 helpers ----------------
__device__ __forceinline__ uint32_t f2tf32(float f) {
    uint32_t r;
    asm("cvt.rna.tf32.f32 %0, %1;" : "=r"(r) : "f"(f));
    return r;
}
__device__ __forceinline__ void mma_tf32_16n8k8(float* d, const uint32_t* a, const uint32_t* b) {
    asm volatile(
        "mma.sync.aligned.m16n8k8.row.col.f32.tf32.tf32.f32 "
        "{%0,%1,%2,%3}, {%4,%5,%6,%7}, {%8,%9}, {%0,%1,%2,%3};"
        : "+f"(d[0]), "+f"(d[1]), "+f"(d[2]), "+f"(d[3])
        : "r"(a[0]), "r"(a[1]), "r"(a[2]), "r"(a[3]), "r"(b[0]), "r"(b[1]));
}
__device__ __forceinline__ int swz(int g) { return g ^ (g >> 3); }

// ---------------- dtype probe + conversion ----------------
__global__ void k_detect64(const void* raw, int count, int nlimit, int* flag) {
    __shared__ int ok;
    if (threadIdx.x == 0) ok = 1;
    __syncthreads();
    int m = count / 2 < 1024 ? count / 2 : 1024;
    const long long* p = (const long long*)raw;
    for (int i = threadIdx.x; i < m; i += blockDim.x) {
        long long v = p[i];
        if (v < 0 || v >= (long long)nlimit) ok = 0;
    }
    __syncthreads();
    if (threadIdx.x == 0) *flag = ok;
}

__global__ void k_convert_count(const void* raw, int E, const int* flag,
                                int* __restrict__ src, int* __restrict__ dst,
                                int* __restrict__ deg) {
    int e0 = (blockIdx.x * blockDim.x + threadIdx.x) * 2;
    if (e0 >= E) return;
    int s0, d0, s1, d1;
    bool two = (e0 + 1 < E);
    if (*flag) {
        const long long* p = (const long long*)raw;
        longlong2 sv = *(const longlong2*)(p + e0);
        longlong2 dv = *(const longlong2*)(p + E + e0);
        s0 = (int)sv.x; s1 = (int)sv.y;
        d0 = (int)dv.x; d1 = (int)dv.y;
    } else {
        const int* p = (const int*)raw;
        s0 = p[e0]; d0 = p[E + e0];
        s1 = two ? p[e0 + 1] : 0;
        d1 = two ? p[E + e0 + 1] : 0;
    }
    src[e0] = s0; dst[e0] = d0;
    atomicAdd(&deg[d0], 1);
    if (two) {
        src[e0 + 1] = s1; dst[e0 + 1] = d1;
        atomicAdd(&deg[d1], 1);
    }
}

__global__ void k_convert_batch(const void* raw, int n, const int* flag, int* __restrict__ b) {
    int i0 = (blockIdx.x * blockDim.x + threadIdx.x) * 4;
    if (i0 >= n) return;
    if (*flag) {
        const long long* p = (const long long*)raw;
#pragma unroll
        for (int q = 0; q < 4; ++q)
            if (i0 + q < n) b[i0 + q] = (int)p[i0 + q];
    } else {
        const int* p = (const int*)raw;
#pragma unroll
        for (int q = 0; q < 4; ++q)
            if (i0 + q < n) b[i0 + q] = p[i0 + q];
    }
}

__global__ void k_zero_int(int* __restrict__ p, int n) {
    int i = blockIdx.x * blockDim.x + threadIdx.x;
    if (i < n) p[i] = 0;
}

// ---------------- preprocess ----------------
__global__ void k_preprocess(const float* __restrict__ x, float* __restrict__ xn, int n) {
    int w = (blockIdx.x * blockDim.x + threadIdx.x) >> 5;
    if (w >= n) return;
    int lane = threadIdx.x & 31;
    float4 v = *(const float4*)(x + (size_t)w * 128 + lane * 4);
    float s = v.x + v.y + v.z + v.w;
#pragma unroll
    for (int o = 16; o > 0; o >>= 1) s += __shfl_xor_sync(0xffffffffu, s, o);
    float rinv = (s != 0.f) ? (1.f / s) : 0.f;
    *(float4*)(xn + (size_t)w * 128 + lane * 4) = make_float4(v.x * rinv, v.y * rinv, v.z * rinv, v.w * rinv);
}

// ---------------- CSR scan: 4 elems/thread, seeds fill cursor in-place -------
__global__ void k_scan_deg(int* __restrict__ deg_fill, int* __restrict__ rowptr, int n) {
    __shared__ int wsum[32];
    __shared__ int s_total;
    int t = threadIdx.x, lane = t & 31, wid = t >> 5;
    int carry = 0;
    for (int base = 0; base < n; base += 4096) {
        int i0 = base + t * 4;
        int v[4];
        if (i0 + 3 < n) {
            int4 d = *(const int4*)(deg_fill + i0);
            v[0] = d.x; v[1] = d.y; v[2] = d.z; v[3] = d.w;
        } else {
#pragma unroll
            for (int q = 0; q < 4; ++q) v[q] = (i0 + q < n) ? deg_fill[i0 + q] : 0;
        }
        int s = v[0] + v[1] + v[2] + v[3];
        int xv = s;
#pragma unroll
        for (int o = 1; o < 32; o <<= 1) {
            int y = __shfl_up_sync(0xffffffffu, xv, o);
            if (lane >= o) xv += y;
        }
        if (lane == 31) wsum[wid] = xv;
        __syncthreads();
        if (wid == 0) {
            int wv = wsum[lane];
#pragma unroll
            for (int o = 1; o < 32; o <<= 1) {
                int y = __shfl_up_sync(0xffffffffu, wv, o);
                if (lane >= o) wv += y;
            }
            wsum[lane] = wv;
            if (lane == 31) s_total = wv;
        }
        __syncthreads();
        int run = carry + (xv - s) + (wid > 0 ? wsum[wid - 1] : 0);
        if (i0 + 3 < n) {
            int4 rp = make_int4(run, run + v[0], run + v[0] + v[1], run + v[0] + v[1] + v[2]);
            *(int4*)(rowptr + i0) = rp;
            *(int4*)(deg_fill + i0) = rp;
        } else {
#pragma unroll
            for (int q = 0; q < 4; ++q) {
                if (i0 + q < n) { rowptr[i0 + q] = run; deg_fill[i0 + q] = run; run += v[q]; }
            }
        }
        carry += s_total;
        __syncthreads();
    }
    if (t == 0) rowptr[n] = carry;
}

__global__ void k_fill_edges(const int* __restrict__ src, const int* __restrict__ dst,
                             int* __restrict__ fillc, int* __restrict__ col, int E) {
    int e = blockIdx.x * blockDim.x + threadIdx.x;
    if (e < E) {
        int p = atomicAdd(&fillc[dst[e]], 1);
        col[p] = src[e];
    }
}

// ---------------- mean aggregation: warp per node, unroll-4 for MLP ----------
__global__ void k_aggregate(const float* __restrict__ xin, const int* __restrict__ rowptr,
                            const int* __restrict__ col, float* __restrict__ outm, int n) {
    int w = (blockIdx.x * blockDim.x + threadIdx.x) >> 5;
    if (w >= n) return;
    int lane = threadIdx.x & 31;
    int s0 = rowptr[w], s1 = rowptr[w + 1];
    float ax = 0.f, ay = 0.f, az = 0.f, aw = 0.f;
    int j = s0;
    for (; j + 3 < s1; j += 4) {
        int i0 = __ldg(&col[j]);
        int i1 = __ldg(&col[j + 1]);
        int i2 = __ldg(&col[j + 2]);
        int i3 = __ldg(&col[j + 3]);
        float4 v0 = *(const float4*)(xin + (size_t)i0 * 128 + lane * 4);
        float4 v1 = *(const float4*)(xin + (size_t)i1 * 128 + lane * 4);
        float4 v2 = *(const float4*)(xin + (size_t)i2 * 128 + lane * 4);
        float4 v3 = *(const float4*)(xin + (size_t)i3 * 128 + lane * 4);
        ax += v0.x + v1.x + v2.x + v3.x;
        ay += v0.y + v1.y + v2.y + v3.y;
        az += v0.z + v1.z + v2.z + v3.z;
        aw += v0.w + v1.w + v2.w + v3.w;
    }
    for (; j < s1; ++j) {
        int s = __ldg(&col[j]);
        float4 v = *(const float4*)(xin + (size_t)s * 128 + lane * 4);
        ax += v.x; ay += v.y; az += v.z; aw += v.w;
    }
    float inv = 1.f / fmaxf((float)(s1 - s0), 1.f);
    *(float4*)(outm + (size_t)w * 128 + lane * 4) = make_float4(ax * inv, ay * inv, az * inv, aw * inv);
}

// ---------------- mma.sync tf32 dual GEMM, frag-order SMEM, 32-col chunks ----
// Wf: [32 k8][16 nt] x 64 floats = 32768 floats
// Af: 2 bufs x [4 k8][8 mt] x 128 floats = 8192 floats
#define SM_WF     0
#define SM_AF0    32768
#define SM_AF1    (SM_AF0 + 4096)
#define SM_BS     (SM_AF1 + 4096)
#define SM_RSS    (SM_BS + 128)
#define SM_FLOATS (SM_RSS + 128)
#define FLAG_LEAKY 1
#define FLAG_NORM  2

__global__ void __launch_bounds__(256, 1)
k_gemm_mma(const float* __restrict__ A0, const float* __restrict__ A1,
           const float* __restrict__ Wa, const float* __restrict__ Wb, int ldw,
           const float* __restrict__ bias, float* __restrict__ out, int n, int flags) {
    extern __shared__ float sm[];
    float* Wf    = sm + SM_WF;
    float* bs    = sm + SM_BS;
    float* rowss = sm + SM_RSS;

    int tid = threadIdx.x, lane = tid & 31, wid = tid >> 5;
    int wm = wid >> 2, wn = wid & 3;

    if (tid < 128) bs[tid] = bias ? bias[tid] : 0.f;

    // stage weights into fragment order (once per CTA)
    for (int it = 0; it < 32; ++it) {
        int idx4 = it * 256 + tid;
        int nn = idx4 >> 6;
        int k4 = (idx4 & 63) * 4;
        float4 v = (k4 < 128) ? *(const float4*)(Wa + (size_t)nn * ldw + k4)
                              : *(const float4*)(Wb + (size_t)nn * ldw + (k4 - 128));
        float vv[4] = {v.x, v.y, v.z, v.w};
#pragma unroll
        for (int q = 0; q < 4; ++q) {
            int k = k4 + q;
            int kb = k >> 3, kc = k & 7, nt = nn >> 3, nl = nn & 7;
            Wf[(kb * 16 + nt) * 64 + (nl * 4 + (kc & 3)) * 2 + (kc >> 2)] = __uint_as_float(f2tf32(vv[q]));
        }
    }
    __syncthreads();

    int numTiles = (n + 127) >> 7;
    int r = tid >> 1, ch = tid & 1;              // row, 16-col half
    int mt_s = r >> 4, lrr = r & 7, rh = (r >> 3) & 1;

    for (int tile = blockIdx.x; tile < numTiles; tile += gridDim.x) {
        int row0 = tile << 7;
        float acc[4][4][4];
#pragma unroll
        for (int i = 0; i < 4; ++i)
#pragma unroll
            for (int j = 0; j < 4; ++j)
#pragma unroll
                for (int q = 0; q < 4; ++q) acc[i][j][q] = 0.f;

        // preload chunk 0 (A0 cols 0..31) into Af0
        {
            const float* rowp = A0 + (size_t)(row0 + r) * 128 + ch * 16;
            float* buf = sm + SM_AF0;
#pragma unroll
            for (int q = 0; q < 4; ++q) {
                float4 v = *(const float4*)(rowp + q * 4);
                float vv[4] = {v.x, v.y, v.z, v.w};
                int blk = (ch * 2 + (q >> 1)) * 8 + mt_s;
                int hh = q & 1;
#pragma unroll
                for (int j = 0; j < 4; ++j)
                    buf[blk * 128 + swz(lrr * 4 + j) * 4 + rh + 2 * hh] = __uint_as_float(f2tf32(vv[j]));
            }
        }
        __syncthreads();

        for (int c = 0; c < 8; ++c) {
            float pv[16];
            if (c < 7) {
                int cn = c + 1;
                const float* srcp = (cn < 4) ? A0 : A1;
                const float* rowp = srcp + (size_t)(row0 + r) * 128 + (cn & 3) * 32 + ch * 16;
#pragma unroll
                for (int q = 0; q < 4; ++q) {
                    float4 v = *(const float4*)(rowp + q * 4);
                    pv[q * 4 + 0] = v.x; pv[q * 4 + 1] = v.y; pv[q * 4 + 2] = v.z; pv[q * 4 + 3] = v.w;
                }
            }
            const float* Ab = sm + ((c & 1) ? SM_AF1 : SM_AF0);
#pragma unroll
            for (int h = 0; h < 4; ++h) {
                int kb = c * 4 + h;
                uint32_t a[4][4], b[4][2];
#pragma unroll
                for (int i = 0; i < 4; ++i) {
                    float4 af = *(const float4*)(Ab + (h * 8 + wm * 4 + i) * 128 + swz(lane) * 4);
                    a[i][0] = __float_as_uint(af.x);
                    a[i][1] = __float_as_uint(af.y);
                    a[i][2] = __float_as_uint(af.z);
                    a[i][3] = __float_as_uint(af.w);
                }
#pragma unroll
                for (int j = 0; j < 4; ++j) {
                    float2 bf = *(const float2*)(Wf + (kb * 16 + wn * 4 + j) * 64 + lane * 2);
                    b[j][0] = __float_as_uint(bf.x);
                    b[j][1] = __float_as_uint(bf.y);
                }
#pragma unroll
                for (int i = 0; i < 4; ++i)
#pragma unroll
                    for (int j = 0; j < 4; ++j)
                        mma_tf32_16n8k8(acc[i][j], a[i], b[j]);
            }
            if (c < 7) {
                float* buf = sm + (((c + 1) & 1) ? SM_AF1 : SM_AF0);
#pragma unroll
                for (int q = 0; q < 4; ++q) {
                    int blk = (ch * 2 + (q >> 1)) * 8 + mt_s;
                    int hh = q & 1;
#pragma unroll
                    for (int j = 0; j < 4; ++j)
                        buf[blk * 128 + swz(lrr * 4 + j) * 4 + rh + 2 * hh] = __uint_as_float(f2tf32(pv[q * 4 + j]));
                }
            }
            __syncthreads();
        }

        // ---------------- epilogue ----------------
        int lr = lane >> 2, lc = lane & 3;
        bool donorm = (flags & FLAG_NORM) != 0;
        if (donorm) {
            if (tid < 128) rowss[tid] = 0.f;
            __syncthreads();
#pragma unroll
            for (int i = 0; i < 4; ++i) {
#pragma unroll
                for (int rh2 = 0; rh2 < 2; ++rh2) {
                    float ss = 0.f;
#pragma unroll
                    for (int j = 0; j < 4; ++j) {
                        float d0 = acc[i][j][rh2 * 2], d1 = acc[i][j][rh2 * 2 + 1];
                        ss += d0 * d0 + d1 * d1;
                    }
                    ss += __shfl_xor_sync(0xffffffffu, ss, 1);
                    ss += __shfl_xor_sync(0xffffffffu, ss, 2);
                    if (lc == 0) atomicAdd(&rowss[wm * 64 + i * 16 + lr + rh2 * 8], ss);
                }
            }
            __syncthreads();
        }
#pragma unroll
        for (int i = 0; i < 4; ++i) {
#pragma unroll
            for (int rh2 = 0; rh2 < 2; ++rh2) {
                int rl = wm * 64 + i * 16 + lr + rh2 * 8;
                int row = row0 + rl;
                if (row >= n) continue;
                float inv = 1.f;
                if (donorm) inv = 1.f / fmaxf(sqrtf(rowss[rl]), 1e-12f);
#pragma unroll
                for (int j = 0; j < 4; ++j) {
                    int colp = wn * 32 + j * 8 + 2 * lc;
                    float v0 = acc[i][j][rh2 * 2] * inv + bs[colp];
                    float v1 = acc[i][j][rh2 * 2 + 1] * inv + bs[colp + 1];
                    v0 = (v0 >= 0.f) ? v0 : 0.01f * v0;
                    v1 = (v1 >= 0.f) ? v1 : 0.01f * v1;
                    *(float2*)(out + (size_t)row * 128 + colp) = make_float2(v0, v1);
                }
            }
        }
        __syncthreads();
    }
}

// ---------------- pool (4 partials per graph) + final ----------------
__global__ void k_pool(const float* __restrict__ hin, const int* __restrict__ batch,
                       float* __restrict__ pooled, int n) {
    int bq = blockIdx.x;
    int g = bq >> 2, q = bq & 3;
    int lo = 0, hi = n;
    while (lo < hi) { int m = (lo + hi) >> 1; if (batch[m] < g) lo = m + 1; else hi = m; }
    int start = lo;
    hi = n;
    while (lo < hi) { int m = (lo + hi) >> 1; if (batch[m] < g + 1) lo = m + 1; else hi = m; }
    int end = lo;
    int len = end - start;
    int qs = start + (len * q) / 4;
    int qe = start + (len * (q + 1)) / 4;
    int f = threadIdx.x;
    float acc = 0.f;
    for (int i = qs; i < qe; ++i) acc += hin[(size_t)i * 128 + f];
    pooled[(size_t)bq * 128 + f] = acc;
}

__global__ void k_final(const float* __restrict__ pooled, const float* __restrict__ W,
                        const float* __restrict__ b, float* __restrict__ outp) {
    __shared__ float pr[128];
    __shared__ float red[128];
    int g = blockIdx.x, hh = threadIdx.x;
    pr[hh] = pooled[(size_t)(g * 4 + 0) * 128 + hh] + pooled[(size_t)(g * 4 + 1) * 128 + hh]
           + pooled[(size_t)(g * 4 + 2) * 128 + hh] + pooled[(size_t)(g * 4 + 3) * 128 + hh];
    __syncthreads();
    float acc = b[hh];
#pragma unroll 8
    for (int k = 0; k < 128; ++k) acc += pr[k] * __ldg(&W[hh * 128 + k]);
    acc = (acc >= 0.f) ? acc : 0.01f * acc;
    red[hh] = acc * acc;
    __syncthreads();
    for (int s = 64; s > 0; s >>= 1) {
        if (hh < s) red[hh] += red[hh + s];
        __syncthreads();
    }
    float inv = 1.f / fmaxf(sqrtf(red[0]), 1e-12f);
    outp[g * 128 + hh] = acc * inv;
}

// ---------------- launcher ----------------
extern "C" void kernel_launch(void* const* d_in, const int* in_sizes, int n_in,
                              void* d_out, int out_size) {
    const float* x         = (const float*)d_in[0];
    const void*  eidx_raw  = d_in[1];
    const void*  batch_raw = d_in[2];
    const float* W1l  = (const float*)d_in[3];
    const float* W1r  = (const float*)d_in[4];
    const float* W2l  = (const float*)d_in[5];
    const float* W2r  = (const float*)d_in[6];
    const float* fc1W = (const float*)d_in[7];
    const float* fc1b = (const float*)d_in[8];
    const float* fc2W = (const float*)d_in[9];
    const float* fc2b = (const float*)d_in[10];
    const float* fc3W = (const float*)d_in[11];
    const float* fc3b = (const float*)d_in[12];
    float* out = (float*)d_out;

    int n = in_sizes[0] / 128;
    int E = in_sizes[1] / 2;

    float *xn, *tb, *h1, *h, *pooled;
    int *rowptr, *fill, *col, *srcA, *dstA, *batch32, *is64;
    cudaGetSymbolAddress((void**)&xn,      g_xn);
    cudaGetSymbolAddress((void**)&tb,      g_t);
    cudaGetSymbolAddress((void**)&h1,      g_h1);
    cudaGetSymbolAddress((void**)&h,       g_h);
    cudaGetSymbolAddress((void**)&pooled,  g_pooled);
    cudaGetSymbolAddress((void**)&rowptr,  g_rowptr);
    cudaGetSymbolAddress((void**)&fill,    g_fill);
    cudaGetSymbolAddress((void**)&col,     g_col);
    cudaGetSymbolAddress((void**)&srcA,    g_src);
    cudaGetSymbolAddress((void**)&dstA,    g_dst);
    cudaGetSymbolAddress((void**)&batch32, g_batch);
    cudaGetSymbolAddress((void**)&is64,    g_is64);
    float* mean;
    cudaGetSymbolAddress((void**)&mean,    g_mean);

    int smemB = SM_FLOATS * (int)sizeof(float);
    cudaFuncSetAttribute(k_gemm_mma, cudaFuncAttributeMaxDynamicSharedMemorySize, smemB);

    int warpBlocks = (n * 32 + 255) / 256;
    int intBlocks  = (n + 255) / 256;
    int edgeBlocks = (E + 255) / 256;
    int pairBlocks = (E / 2 + 255) / 256;
    int b4Blocks   = (n / 4 + 255) / 256 + 1;
    int gemmGrid   = 148;

    k_detect64<<<1, 256>>>(eidx_raw, 2 * E, n, is64);
    k_zero_int<<<intBlocks, 256>>>(fill, n);
    k_convert_count<<<pairBlocks, 256>>>(eidx_raw, E, is64, srcA, dstA, fill);
    k_convert_batch<<<b4Blocks, 256>>>(batch_raw, n, is64, batch32);

    k_preprocess<<<warpBlocks, 256>>>(x, xn, n);

    k_scan_deg<<<1, 1024>>>(fill, rowptr, n);
    k_fill_edges<<<edgeBlocks, 256>>>(srcA, dstA, fill, col, E);

    // conv1
    k_aggregate<<<warpBlocks, 256>>>(xn, rowptr, col, mean, n);
    k_gemm_mma<<<gemmGrid, 256, smemB>>>(mean, xn, W1l, W1r, 128, nullptr, h1, n, FLAG_LEAKY | FLAG_NORM);

    // fc1
    k_gemm_mma<<<gemmGrid, 256, smemB>>>(h1, xn, fc1W, fc1W + 128, 256, fc1b, h, n, FLAG_LEAKY);

    // conv2
    k_aggregate<<<warpBlocks, 256>>>(h, rowptr, col, mean, n);
    k_gemm_mma<<<gemmGrid, 256, smemB>>>(mean, h, W2l, W2r, 128, nullptr, h1, n, FLAG_LEAKY | FLAG_NORM);

    // fc2
    k_gemm_mma<<<gemmGrid, 256, smemB>>>(h1, h, fc2W, fc2W + 128, 256, fc2b, tb, n, FLAG_LEAKY);

    // pool + final
    k_pool<<<GMAX * 4, 128>>>(tb, batch32, pooled, n);
    k_final<<<GMAX, 128>>>(pooled, fc3W, fc3b, out);
}